// round 4
// baseline (speedup 1.0000x reference)
#include <cuda_runtime.h>
#include <cstdint>

#define DEV __device__ __forceinline__

// ---------------- problem constants ----------------
constexpr int NN   = 10000;
constexpr int FIN  = 512;
constexpr int HID  = 256;
constexpr int NCLS = 64;
constexpr int SPLITK = 4;

// ---------------- scratch ----------------
static __device__ float g_S1p[NN * HID];          // S1 permuted (pi128), tf32
static __device__ float g_S2p[NN * NCLS];         // S2 permuted (pi64), tf32
static __device__ float g_W1p[FIN * HID];         // W1 permuted, tf32
static __device__ float g_W2p[HID * NCLS];        // W2 permuted, tf32
static __device__ float g_part[SPLITK * NN * NCLS]; // split-K partials of adj@S2

// ---------------- helpers ----------------
DEV float rna(float x) {
    uint32_t u;
    asm("cvt.rna.tf32.f32 %0, %1;" : "=r"(u) : "f"(x));
    return __uint_as_float(u);
}

DEV void cp16z(void* smem, const void* gmem, int sz) {
    uint32_t s = (uint32_t)__cvta_generic_to_shared(smem);
    asm volatile("cp.async.cg.shared.global [%0], [%1], 16, %2;" :: "r"(s), "l"(gmem), "r"(sz));
}
DEV void cp_commit() { asm volatile("cp.async.commit_group;"); }
template <int NG> DEV void cp_wait() { asm volatile("cp.async.wait_group %0;" :: "n"(NG)); }

// m16n8k8 tf32 mma; operands raw fp32 bits (pre-rounded where needed)
DEV void mma8(float* c, const float* a, float b0f, float b1f) {
    uint32_t a0 = __float_as_uint(a[0]), a1 = __float_as_uint(a[1]);
    uint32_t a2 = __float_as_uint(a[2]), a3 = __float_as_uint(a[3]);
    uint32_t b0 = __float_as_uint(b0f), b1 = __float_as_uint(b1f);
    asm volatile(
        "mma.sync.aligned.m16n8k8.row.col.f32.tf32.tf32.f32 "
        "{%0,%1,%2,%3},{%4,%5,%6,%7},{%8,%9},{%0,%1,%2,%3};"
        : "+f"(c[0]), "+f"(c[1]), "+f"(c[2]), "+f"(c[3])
        : "r"(a0), "r"(a1), "r"(a2), "r"(a3), "r"(b0), "r"(b1));
}

// ============================================================================
// TF32 mma.sync GEMM:  C[M,N] = A[M,K] @ B[K,N]  (B column-permuted per BN blk)
// 256 threads, 8 warps as 4(M) x 2(N). BK=16, 4-stage cp.async pipeline.
// Warp tile (BM/4) x (BN/2).
// EPI: 0 raw ; 1 bias+relu+rna ; 3 rna.   PERM: 0 plain ; else pi-store.
// CVTA: 1 -> round A fragments to tf32 (rna) before mma.
// Split-K via blockIdx.z (partials at C + z*M*N).
// ============================================================================
template <int BM, int BN, int EPI, int PERM, int CVTA>
__global__ __launch_bounds__(256, 3)
void gemm_mma(const float* __restrict__ A, const float* __restrict__ B,
              const float* __restrict__ bias, float* __restrict__ C,
              int M, int N, int K)
{
    constexpr int BK = 16, STAGES = 4;
    constexpr int WM = BM / 4, WN = BN / 2;
    constexpr int MF = WM / 16, NF = WN / 8;
    constexpr int ASTRIDE = 20;
    constexpr int BSTRIDE = BN + 4;
    constexpr int AWORDS = BM * ASTRIDE;
    constexpr int SW = AWORDS + BK * BSTRIDE;

    extern __shared__ float sm[];

    const int tid  = threadIdx.x;
    const int warp = tid >> 5;
    const int lane = tid & 31;
    const int wm = warp & 3;           // 0..3 -> rows wm*WM
    const int wn = warp >> 2;          // 0..1 -> cols wn*WN
    const int g = lane >> 2;           // 0..7
    const int tig = lane & 3;

    const int bm = blockIdx.y * BM;
    const int bn = blockIdx.x * BN;

    // split-K range
    const int z  = blockIdx.z;
    const int kh = (gridDim.z == 1) ? K : (((K / gridDim.z) + 15) & ~15);
    const int k0 = z * kh;
    const int ksz = (K - k0 < kh) ? (K - k0) : kh;
    float* Cz = C + (long long)z * M * N;

    auto load_stage = [&](int stg, int kk) {
        float* As = sm + stg * SW;
        float* Bs = As + AWORDS;
        const int ar = tid >> 2;          // 0..63
        const int ac = (tid & 3) * 4;
        #pragma unroll
        for (int i = 0; i < BM / 64; ++i) {
            int r = ar + i * 64;
            int grow = bm + r;
            int sz = (grow < M) ? 16 : 0;
            const float* src = A + (long long)((grow < M) ? grow : 0) * K + k0 + kk + ac;
            cp16z(As + r * ASTRIDE + ac, src, sz);
        }
        if (BN == 128) {
            const int br = tid >> 5;      // 0..7
            const int bc = (tid & 31) * 4;
            #pragma unroll
            for (int j = 0; j < 2; ++j) {
                int kr = br + j * 8;
                const float* src = B + (long long)(k0 + kk + kr) * N + bn + bc;
                cp16z(Bs + kr * BSTRIDE + bc, src, 16);
            }
        } else {
            const int br = tid >> 4;      // 0..15
            const int bc = (tid & 15) * 4;
            const float* src = B + (long long)(k0 + kk + br) * N + bn + bc;
            cp16z(Bs + br * BSTRIDE + bc, src, 16);
        }
        cp_commit();
    };

    float acc[MF][NF][4];
    #pragma unroll
    for (int i = 0; i < MF; ++i)
        #pragma unroll
        for (int j = 0; j < NF; ++j)
            #pragma unroll
            for (int k = 0; k < 4; ++k) acc[i][j][k] = 0.f;

    const int goff = g * (BN / 8) + wn * NF;

    auto compute_stage = [&](int stg) {
        const float* As = sm + stg * SW;
        const float* Bs = As + AWORDS;
        #pragma unroll
        for (int ks = 0; ks < BK; ks += 8) {
            float a[MF][4];
            #pragma unroll
            for (int mf = 0; mf < MF; ++mf) {
                const float* ap = As + (wm * WM + mf * 16 + g) * ASTRIDE + ks + tig;
                a[mf][0] = ap[0];
                a[mf][1] = ap[8 * ASTRIDE];
                a[mf][2] = ap[4];
                a[mf][3] = ap[8 * ASTRIDE + 4];
                if (CVTA) {
                    a[mf][0] = rna(a[mf][0]); a[mf][1] = rna(a[mf][1]);
                    a[mf][2] = rna(a[mf][2]); a[mf][3] = rna(a[mf][3]);
                }
            }
            const float* bp0 = Bs + (ks + tig) * BSTRIDE + goff;
            const float* bp1 = bp0 + 4 * BSTRIDE;
            #pragma unroll
            for (int q = 0; q < NF / 4; ++q) {
                float4 bl0 = *reinterpret_cast<const float4*>(bp0 + 4 * q);
                float4 bl1 = *reinterpret_cast<const float4*>(bp1 + 4 * q);
                #pragma unroll
                for (int mf = 0; mf < MF; ++mf) {
                    mma8(acc[mf][4 * q + 0], a[mf], bl0.x, bl1.x);
                    mma8(acc[mf][4 * q + 1], a[mf], bl0.y, bl1.y);
                    mma8(acc[mf][4 * q + 2], a[mf], bl0.z, bl1.z);
                    mma8(acc[mf][4 * q + 3], a[mf], bl0.w, bl1.w);
                }
            }
        }
    };

    // ---- 4-stage pipeline ----
    const int KT = ksz / BK;
    #pragma unroll
    for (int s = 0; s < STAGES - 1; ++s) load_stage(s, s * BK);

    for (int kt = 0; kt < KT; ++kt) {
        cp_wait<STAGES - 2>();
        __syncthreads();
        const int nk = kt + STAGES - 1;
        if (nk < KT) load_stage(nk % STAGES, nk * BK);
        else cp_commit();   // keep group accounting for the drain
        compute_stage(kt % STAGES);
    }

    // ---- epilogue ----
    #pragma unroll
    for (int mf = 0; mf < MF; ++mf) {
        #pragma unroll
        for (int nf = 0; nf < NF; ++nf) {
            const int l = wn * WN + nf * 8 + 2 * tig;
            const int c = bn + l;
            float bv0 = 0.f, bv1 = 0.f;
            if (EPI == 1) { bv0 = bias[c]; bv1 = bias[c + 1]; }
            #pragma unroll
            for (int h = 0; h < 2; ++h) {
                const int r = bm + wm * WM + mf * 16 + g + h * 8;
                if (r >= M) continue;
                float v0 = acc[mf][nf][2 * h];
                float v1 = acc[mf][nf][2 * h + 1];
                if (EPI == 1) {
                    v0 = fmaxf(v0 + bv0, 0.f);
                    v1 = fmaxf(v1 + bv1, 0.f);
                }
                if (EPI == 1 || EPI == 3) { v0 = rna(v0); v1 = rna(v1); }
                if (PERM == 0) {
                    *reinterpret_cast<float2*>(&Cz[(long long)r * N + c]) = make_float2(v0, v1);
                } else {
                    const int p = (l & 7) * (PERM / 8) + (l >> 3);
                    Cz[(long long)r * N + bn + p] = v0;
                    Cz[(long long)r * N + bn + p + PERM / 8] = v1;
                }
            }
        }
    }
}

// ---------------- weight permute (+rna) -------------------------------------
template <int BLK>
__global__ void permW(const float* __restrict__ in, float* __restrict__ out, int R, int C) {
    int i = blockIdx.x * blockDim.x + threadIdx.x;
    if (i < R * C) {
        int c = i % C;
        int cl = c & (BLK - 1);
        int cb = c - cl;
        int p = (cl & 7) * (BLK / 8) + (cl >> 3);
        out[(i - c) + cb + p] = rna(in[i]);
    }
}

// ---------------- combine split-K partials + bias + log-softmax -------------
__global__ void lsm_combine(const float* __restrict__ part, const float* __restrict__ b2,
                            float* __restrict__ out, int M) {
    int w = (int)((blockIdx.x * blockDim.x + threadIdx.x) >> 5);
    int lane = threadIdx.x & 31;
    if (w >= M) return;
    const long long base = (long long)w * 64;
    const long long strd = (long long)M * 64;
    float x0 = b2[lane], x1 = b2[lane + 32];
    #pragma unroll
    for (int p = 0; p < SPLITK; ++p) {
        x0 += part[p * strd + base + lane];
        x1 += part[p * strd + base + lane + 32];
    }
    float m = fmaxf(x0, x1);
    #pragma unroll
    for (int o = 16; o > 0; o >>= 1) m = fmaxf(m, __shfl_xor_sync(0xffffffffu, m, o));
    float s = expf(x0 - m) + expf(x1 - m);
    #pragma unroll
    for (int o = 16; o > 0; o >>= 1) s += __shfl_xor_sync(0xffffffffu, s, o);
    float l = m + logf(s);
    out[base + lane]      = x0 - l;
    out[base + lane + 32] = x1 - l;
}

// ---------------- launch ----------------
extern "C" void kernel_launch(void* const* d_in, const int* in_sizes, int n_in,
                              void* d_out, int out_size) {
    const float* feature = (const float*)d_in[0];   // [10000, 512]
    const float* adj     = (const float*)d_in[1];   // [10000, 10000]
    const float* W1      = (const float*)d_in[2];   // [512, 256]
    const float* b1      = (const float*)d_in[3];   // [256]
    const float* W2      = (const float*)d_in[4];   // [256, 64]
    const float* b2      = (const float*)d_in[5];   // [64]

    float* out = (float*)d_out;
    float* x1  = out;                               // [10000, 256]
    float* lsm = out + (long long)NN * HID;         // [10000, 64]

    float *S1p, *S2p, *W1p, *W2p, *part;
    cudaGetSymbolAddress((void**)&S1p, g_S1p);
    cudaGetSymbolAddress((void**)&S2p, g_S2p);
    cudaGetSymbolAddress((void**)&W1p, g_W1p);
    cudaGetSymbolAddress((void**)&W2p, g_W2p);
    cudaGetSymbolAddress((void**)&part, g_part);

    //                      BM   BN  EPI PERM CVTA
    auto* G0 = gemm_mma<64, 128, 3, 128, 1>;   // feature @ W1p -> S1p
    auto* G1 = gemm_mma<64, 128, 1, 0,   1>;   // adj @ S1p -> x1 (bias+relu)
    auto* G2 = gemm_mma<64, 64,  3, 64,  0>;   // x1 @ W2p -> S2p
    auto* G3 = gemm_mma<128, 64, 0, 0,   1>;   // adj @ S2p -> partials (split-K)

    constexpr int SW128 = (64 * 20 + 16 * 132) * 4;    // 13568 B/stage
    constexpr int SW64  = (64 * 20 + 16 * 68) * 4;     // 9472
    constexpr int SWG3  = (128 * 20 + 16 * 68) * 4;    // 14592
    constexpr int SM_G01 = 4 * SW128;                  // 54272
    constexpr int SM_G2  = 4 * SW64;                   // 37888
    constexpr int SM_G3  = 4 * SWG3;                   // 58368

    cudaFuncSetAttribute(G0, cudaFuncAttributeMaxDynamicSharedMemorySize, SM_G01);
    cudaFuncSetAttribute(G1, cudaFuncAttributeMaxDynamicSharedMemorySize, SM_G01);
    cudaFuncSetAttribute(G2, cudaFuncAttributeMaxDynamicSharedMemorySize, SM_G2);
    cudaFuncSetAttribute(G3, cudaFuncAttributeMaxDynamicSharedMemorySize, SM_G3);

    const int MT64 = (NN + 63) / 64;     // 157
    const int MT128 = (NN + 127) / 128;  // 79

    permW<128><<<(FIN * HID + 255) / 256, 256>>>(W1, W1p, FIN, HID);
    permW<64><<<(HID * NCLS + 255) / 256, 256>>>(W2, W2p, HID, NCLS);

    // G0: S1p = pi128(rna(feature @ W1p))             [10000, 256]
    G0<<<dim3(HID / 128, MT64, 1), 256, SM_G01>>>(feature, W1p, nullptr, S1p, NN, HID, FIN);
    // G1: X1 = rna(relu(adj @ S1p + b1)) -> d_out     [10000, 256]
    G1<<<dim3(HID / 128, MT64, 1), 256, SM_G01>>>(adj, S1p, b1, x1, NN, HID, NN);
    // G2: S2p = pi64(rna(X1 @ W2p))                   [10000, 64]
    G2<<<dim3(1, MT64, 1), 256, SM_G2>>>(x1, W2p, nullptr, S2p, NN, NCLS, HID);
    // G3: part[z] = adj @ S2p  (split-K = 4)          [4][10000, 64]
    G3<<<dim3(1, MT128, SPLITK), 256, SM_G3>>>(adj, S2p, nullptr, part, NN, NCLS, NN);
    // combine + bias + log-softmax
    lsm_combine<<<(NN * 32 + 255) / 256, 256>>>(part, b2, lsm, NN);
}

// round 6
// speedup vs baseline: 1.1488x; 1.1488x over previous
#include <cuda_runtime.h>
#include <cstdint>

#define DEV __device__ __forceinline__

// ---------------- problem constants ----------------
constexpr int NN   = 10000;
constexpr int FIN  = 512;
constexpr int HID  = 256;
constexpr int NCLS = 64;
constexpr int KS1  = 4;     // split-K for G1 (adj @ S1)
constexpr int KS3  = 4;     // split-K for G3 (adj @ S2)

// ---------------- scratch ----------------
static __device__ float g_S1p[NN * HID];            // S1 permuted (pi128 per block), tf32
static __device__ float g_S2p[NN * NCLS];           // S2 permuted (pi64), tf32
static __device__ float g_W1p[FIN * HID];           // W1 permuted, tf32
static __device__ float g_W2p[HID * NCLS];          // W2 permuted, tf32
static __device__ float g_p1[KS1 * NN * HID];       // G1 split-K partials
static __device__ float g_p3[KS3 * NN * NCLS];      // G3 split-K partials

// ---------------- helpers ----------------
DEV float rna(float x) {
    uint32_t u;
    asm("cvt.rna.tf32.f32 %0, %1;" : "=r"(u) : "f"(x));
    return __uint_as_float(u);
}

DEV void cp16z(void* smem, const void* gmem, int sz) {
    uint32_t s = (uint32_t)__cvta_generic_to_shared(smem);
    asm volatile("cp.async.cg.shared.global [%0], [%1], 16, %2;" :: "r"(s), "l"(gmem), "r"(sz));
}
DEV void cp_commit() { asm volatile("cp.async.commit_group;"); }
template <int NG> DEV void cp_wait() { asm volatile("cp.async.wait_group %0;" :: "n"(NG)); }

// m16n8k8 tf32 mma
DEV void mma8(float* c, const float* a, float b0f, float b1f) {
    uint32_t a0 = __float_as_uint(a[0]), a1 = __float_as_uint(a[1]);
    uint32_t a2 = __float_as_uint(a[2]), a3 = __float_as_uint(a[3]);
    uint32_t b0 = __float_as_uint(b0f), b1 = __float_as_uint(b1f);
    asm volatile(
        "mma.sync.aligned.m16n8k8.row.col.f32.tf32.tf32.f32 "
        "{%0,%1,%2,%3},{%4,%5,%6,%7},{%8,%9},{%0,%1,%2,%3};"
        : "+f"(c[0]), "+f"(c[1]), "+f"(c[2]), "+f"(c[3])
        : "r"(a0), "r"(a1), "r"(a2), "r"(a3), "r"(b0), "r"(b1));
}

// ============================================================================
// TF32 mma.sync GEMM:  C[M,N] = A[M,K] @ B[K,N]  (B pre-permuted in gmem)
// BM=64. Warp tile fixed 32x64 (THREADS=256, BN=256) or 32x32 (128thr, BN=64).
// Warp grid: wm = warp&1 (2 M-warps), wn = warp>>1 (N-warps).
// B smem layout (conflict-free, verified per-LDS.128-phase):
//   BN=256: two pi128 blocks of 132 floats, row stride 268.
//   BN=64 : 8 groups of 8 floats in 16-float slots, row stride 132.
// EPI: 0 raw ; 3 rna.   PERM: 0 plain ; 64/128 pi-store.  CVTA: rna on A frags.
// Split-K via blockIdx.z -> C + z*M*N.
// ============================================================================
template <int BM, int BN, int THREADS, int STAGES, int EPI, int PERM, int CVTA,
          int MINCTA>
__global__ __launch_bounds__(THREADS, MINCTA)
void gemm_mma(const float* __restrict__ A, const float* __restrict__ B,
              float* __restrict__ C, int M, int N, int K)
{
    constexpr int BK = 16;
    constexpr int NWN = THREADS / 64;          // 4 (256thr) or 2 (128thr)
    constexpr int WM = BM / 2;                 // 32
    constexpr int WN = BN / NWN;               // 64 or 32
    constexpr int MF = WM / 16;                // 2
    constexpr int NF = WN / 8;                 // 8 or 4
    constexpr int ASTRIDE = 20;
    constexpr int BSTRIDE = (BN == 256) ? 268 : 132;
    constexpr int AWORDS = BM * ASTRIDE;
    constexpr int SW = AWORDS + BK * BSTRIDE;

    extern __shared__ float sm[];

    const int tid  = threadIdx.x;
    const int warp = tid >> 5;
    const int lane = tid & 31;
    const int wm = warp & 1;
    const int wn = warp >> 1;
    const int g = lane >> 2;
    const int tig = lane & 3;

    const int bm = blockIdx.y * BM;

    const int z  = blockIdx.z;
    const int kh = (gridDim.z == 1) ? K : (((K / gridDim.z) + 15) & ~15);
    const int k0 = z * kh;
    const int ksz = (K - k0 < kh) ? (K - k0) : kh;
    float* Cz = C + (long long)z * M * N;

    auto load_stage = [&](int stg, int kk) {
        float* As = sm + stg * SW;
        float* Bs = As + AWORDS;
        // A tile: BM rows x 16 floats = BM*4 chunks of 16B
        #pragma unroll
        for (int i = 0; i < (BM * 4) / THREADS; ++i) {
            int c = tid + i * THREADS;
            int r = c >> 2, col = (c & 3) * 4;
            int grow = bm + r;
            int sz = (grow < M) ? 16 : 0;
            const float* src = A + (long long)((grow < M) ? grow : 0) * K + k0 + kk + col;
            cp16z(As + r * ASTRIDE + col, src, sz);
        }
        // B tile: 16 k-rows x BN floats = 4*BN chunks of 16B
        #pragma unroll
        for (int i = 0; i < (4 * BN) / THREADS; ++i) {
            int c = tid + i * THREADS;
            int r = c / (BN / 4);
            int col = (c % (BN / 4)) * 4;
            int dcol;
            if (BN == 256) dcol = (col >> 7) * 132 + (col & 127);
            else           dcol = (col >> 3) * 16 + (col & 7);
            const float* src = B + (long long)(k0 + kk + r) * N + col;
            cp16z(Bs + r * BSTRIDE + dcol, src, 16);
        }
        cp_commit();
    };

    float acc[MF][NF][4];
    #pragma unroll
    for (int i = 0; i < MF; ++i)
        #pragma unroll
        for (int j = 0; j < NF; ++j)
            #pragma unroll
            for (int k = 0; k < 4; ++k) acc[i][j][k] = 0.f;

    const int goff = (BN == 256) ? ((wn >> 1) * 132 + g * 16 + (wn & 1) * 8)
                                 : (g * 16 + wn * 4);

    auto compute_stage = [&](int stg) {
        const float* As = sm + stg * SW;
        const float* Bs = As + AWORDS;
        #pragma unroll
        for (int ks = 0; ks < BK; ks += 8) {
            float a[MF][4];
            #pragma unroll
            for (int mf = 0; mf < MF; ++mf) {
                const float* ap = As + (wm * WM + mf * 16 + g) * ASTRIDE + ks + tig;
                a[mf][0] = ap[0];
                a[mf][1] = ap[8 * ASTRIDE];
                a[mf][2] = ap[4];
                a[mf][3] = ap[8 * ASTRIDE + 4];
                if (CVTA) {
                    a[mf][0] = rna(a[mf][0]); a[mf][1] = rna(a[mf][1]);
                    a[mf][2] = rna(a[mf][2]); a[mf][3] = rna(a[mf][3]);
                }
            }
            const float* bp0 = Bs + (ks + tig) * BSTRIDE + goff;
            const float* bp1 = bp0 + 4 * BSTRIDE;
            #pragma unroll
            for (int q = 0; q < NF / 4; ++q) {
                float4 bl0 = *reinterpret_cast<const float4*>(bp0 + 4 * q);
                float4 bl1 = *reinterpret_cast<const float4*>(bp1 + 4 * q);
                #pragma unroll
                for (int mf = 0; mf < MF; ++mf) {
                    mma8(acc[mf][4 * q + 0], a[mf], bl0.x, bl1.x);
                    mma8(acc[mf][4 * q + 1], a[mf], bl0.y, bl1.y);
                    mma8(acc[mf][4 * q + 2], a[mf], bl0.z, bl1.z);
                    mma8(acc[mf][4 * q + 3], a[mf], bl0.w, bl1.w);
                }
            }
        }
    };

    const int KT = ksz / BK;
    #pragma unroll
    for (int s = 0; s < STAGES - 1; ++s) {
        if (s < KT) load_stage(s, s * BK);
        else cp_commit();
    }

    for (int kt = 0; kt < KT; ++kt) {
        cp_wait<STAGES - 2>();
        __syncthreads();
        const int nk = kt + STAGES - 1;
        if (nk < KT) load_stage(nk % STAGES, nk * BK);
        else cp_commit();
        compute_stage(kt % STAGES);
    }

    // ---- epilogue ----
    #pragma unroll
    for (int mf = 0; mf < MF; ++mf) {
        #pragma unroll
        for (int nf = 0; nf < NF; ++nf) {
            const int l = wn * WN + nf * 8 + 2 * tig;   // local col (even)
            #pragma unroll
            for (int h = 0; h < 2; ++h) {
                const int r = bm + wm * WM + mf * 16 + g + h * 8;
                if (r >= M) continue;
                float v0 = acc[mf][nf][2 * h];
                float v1 = acc[mf][nf][2 * h + 1];
                if (EPI == 3) { v0 = rna(v0); v1 = rna(v1); }
                if (PERM == 0) {
                    *reinterpret_cast<float2*>(&Cz[(long long)r * N + l]) = make_float2(v0, v1);
                } else {
                    const int blk = l & ~(PERM - 1);
                    const int lb  = l & (PERM - 1);
                    const int p = blk + (lb & 7) * (PERM / 8) + (lb >> 3);
                    Cz[(long long)r * N + p] = v0;
                    Cz[(long long)r * N + p + PERM / 8] = v1;
                }
            }
        }
    }
}

// ---------------- weight permute (+rna) -------------------------------------
template <int BLK>
__global__ void permW(const float* __restrict__ in, float* __restrict__ out, int R, int C) {
    int i = blockIdx.x * blockDim.x + threadIdx.x;
    if (i < R * C) {
        int c = i % C;
        int cl = c & (BLK - 1);
        int cb = c - cl;
        int p = (cl & 7) * (BLK / 8) + (cl >> 3);
        out[(i - c) + cb + p] = rna(in[i]);
    }
}

// ---------------- G1 combine: x1 = rna(relu(sum(partials) + b1)) ------------
__global__ void combine_x1(const float* __restrict__ part, const float* __restrict__ b1,
                           float* __restrict__ x1) {
    const int idx = blockIdx.x * blockDim.x + threadIdx.x;   // float4 index
    const int total = NN * HID / 4;
    if (idx >= total) return;
    const float4* p = reinterpret_cast<const float4*>(part);
    float4 s = p[idx];
    #pragma unroll
    for (int z = 1; z < KS1; ++z) {
        float4 t = p[idx + z * total];
        s.x += t.x; s.y += t.y; s.z += t.z; s.w += t.w;
    }
    float4 b = reinterpret_cast<const float4*>(b1)[idx & (HID / 4 - 1)];
    s.x = rna(fmaxf(s.x + b.x, 0.f));
    s.y = rna(fmaxf(s.y + b.y, 0.f));
    s.z = rna(fmaxf(s.z + b.z, 0.f));
    s.w = rna(fmaxf(s.w + b.w, 0.f));
    reinterpret_cast<float4*>(x1)[idx] = s;
}

// ---------------- combine G3 partials + bias + log-softmax ------------------
__global__ void lsm_combine(const float* __restrict__ part, const float* __restrict__ b2,
                            float* __restrict__ out, int M) {
    int w = (int)((blockIdx.x * blockDim.x + threadIdx.x) >> 5);
    int lane = threadIdx.x & 31;
    if (w >= M) return;
    const long long base = (long long)w * 64;
    const long long strd = (long long)M * 64;
    float x0 = b2[lane], x1 = b2[lane + 32];
    #pragma unroll
    for (int p = 0; p < KS3; ++p) {
        x0 += part[p * strd + base + lane];
        x1 += part[p * strd + base + lane + 32];
    }
    float m = fmaxf(x0, x1);
    #pragma unroll
    for (int o = 16; o > 0; o >>= 1) m = fmaxf(m, __shfl_xor_sync(0xffffffffu, m, o));
    float s = expf(x0 - m) + expf(x1 - m);
    #pragma unroll
    for (int o = 16; o > 0; o >>= 1) s += __shfl_xor_sync(0xffffffffu, s, o);
    float l = m + logf(s);
    out[base + lane]      = x0 - l;
    out[base + lane + 32] = x1 - l;
}

// ---------------- launch ----------------
extern "C" void kernel_launch(void* const* d_in, const int* in_sizes, int n_in,
                              void* d_out, int out_size) {
    const float* feature = (const float*)d_in[0];   // [10000, 512]
    const float* adj     = (const float*)d_in[1];   // [10000, 10000]
    const float* W1      = (const float*)d_in[2];   // [512, 256]
    const float* b1      = (const float*)d_in[3];   // [256]
    const float* W2      = (const float*)d_in[4];   // [256, 64]
    const float* b2      = (const float*)d_in[5];   // [64]

    float* out = (float*)d_out;
    float* x1  = out;                               // [10000, 256]
    float* lsm = out + (long long)NN * HID;         // [10000, 64]

    float *S1p, *S2p, *W1p, *W2p, *p1, *p3;
    cudaGetSymbolAddress((void**)&S1p, g_S1p);
    cudaGetSymbolAddress((void**)&S2p, g_S2p);
    cudaGetSymbolAddress((void**)&W1p, g_W1p);
    cudaGetSymbolAddress((void**)&W2p, g_W2p);
    cudaGetSymbolAddress((void**)&p1, g_p1);
    cudaGetSymbolAddress((void**)&p3, g_p3);

    //                  BM  BN   THR STG EPI PERM CVTA MIN
    auto* G0 = gemm_mma<64, 256, 256, 5,  3,  128, 1,   2>;  // feature@W1p -> S1p
    auto* G1 = gemm_mma<64, 256, 256, 5,  0,  0,   1,   2>;  // adj@S1p -> p1 (splitK)
    auto* G2 = gemm_mma<64, 64,  128, 4,  3,  64,  0,   4>;  // x1@W2p -> S2p
    auto* G3 = gemm_mma<64, 64,  128, 4,  0,  0,   1,   4>;  // adj@S2p -> p3 (splitK)

    constexpr int SM256 = 5 * (64 * 20 + 16 * 268) * 4;   // 111360
    constexpr int SM64  = 4 * (64 * 20 + 16 * 132) * 4;   // 54272

    cudaFuncSetAttribute(G0, cudaFuncAttributeMaxDynamicSharedMemorySize, SM256);
    cudaFuncSetAttribute(G1, cudaFuncAttributeMaxDynamicSharedMemorySize, SM256);
    cudaFuncSetAttribute(G2, cudaFuncAttributeMaxDynamicSharedMemorySize, SM64);
    cudaFuncSetAttribute(G3, cudaFuncAttributeMaxDynamicSharedMemorySize, SM64);

    const int MT = (NN + 63) / 64;   // 157

    permW<128><<<(FIN * HID + 255) / 256, 256>>>(W1, W1p, FIN, HID);
    permW<64><<<(HID * NCLS + 255) / 256, 256>>>(W2, W2p, HID, NCLS);

    // G0: S1p = pi128(rna(feature @ W1p))             [10000, 256]
    G0<<<dim3(1, MT, 1), 256, SM256>>>(feature, W1p, S1p, NN, HID, FIN);
    // G1: p1[z] = adj @ S1p  (split-K = 4)            [4][10000, 256]
    G1<<<dim3(1, MT, KS1), 256, SM256>>>(adj, S1p, p1, NN, HID, NN);
    // combine: x1 = rna(relu(sum p1 + b1)) -> d_out
    combine_x1<<<(NN * HID / 4 + 255) / 256, 256>>>(p1, b1, x1);
    // G2: S2p = pi64(rna(x1 @ W2p))                   [10000, 64]
    G2<<<dim3(1, MT, 1), 128, SM64>>>(x1, W2p, S2p, NN, NCLS, HID);
    // G3: p3[z] = adj @ S2p  (split-K = 4)            [4][10000, 64]
    G3<<<dim3(1, MT, KS3), 128, SM64>>>(adj, S2p, p3, NN, NCLS, NN);
    // combine + bias + log-softmax
    lsm_combine<<<(NN * 32 + 255) / 256, 256>>>(p3, b2, lsm, NN);
}